// round 10
// baseline (speedup 1.0000x reference)
#include <cuda_runtime.h>
#include <cuda_bf16.h>

// ForwardKinematics: B=524288, NA=7 joints, NJ=8 transforms.
// out[n] = M0*...*M6*F7, Mi = Fi*[[R(theta_i,a_i),0],[0,1]]
// rot(Mi) = A_i + sin*(A_i K_i) + (1-cos)*(A_i(aa^T) - A_i); trans(Mi)=t_i.
//
// R10: (a) prep kernel writes constants DIRECTLY to the __constant__ symbol's
// backing store (cudaGetSymbolAddress) -> drops the memcpy graph node.
// (b) constants laid out as float4 so each read is one LDCU.128 instead of
// four scalar LDCUs (~201 -> ~70 const loads per warp). fk math unchanged
// from R9 (scalar chain, cbank operands, F7 folded into joint 6).

#define NACT 7
#define THREADS 256

// float4 layout: per joint i (i=0..6), base = i*10:
//   [0..2]  A rows   (9 floats + 3 pad)
//   [3..5]  B = A@K
//   [6..8]  C = A@(aa^T) - A
//   [9]     t (joints 0..5) / at (joint 6, F7-folded affine part)
// [70] bt (joint 6), [71] ct (joint 6)
#define CST4_SIZE 72
__constant__ float4 cst4[CST4_SIZE];

__global__ void prep_kernel(const float* __restrict__ ft,
                            const float* __restrict__ axes,
                            float* __restrict__ csym)   // = &cst4 backing store
{
    const int tid = threadIdx.x;
    if (tid >= NACT) return;

    const float* F = ft + tid * 16;
    float A[9], Bm[9], Cm[9];
    #pragma unroll
    for (int r = 0; r < 3; r++)
        #pragma unroll
        for (int c = 0; c < 3; c++)
            A[r * 3 + c] = F[r * 4 + c];
    const float ax = axes[tid * 3 + 0];
    const float ay = axes[tid * 3 + 1];
    const float az = axes[tid * 3 + 2];
    #pragma unroll
    for (int r = 0; r < 3; r++) {
        Bm[r * 3 + 0] = A[r * 3 + 1] * az - A[r * 3 + 2] * ay;
        Bm[r * 3 + 1] = A[r * 3 + 2] * ax - A[r * 3 + 0] * az;
        Bm[r * 3 + 2] = A[r * 3 + 0] * ay - A[r * 3 + 1] * ax;
    }
    #pragma unroll
    for (int r = 0; r < 3; r++) {
        float dp = A[r * 3 + 0] * ax + A[r * 3 + 1] * ay + A[r * 3 + 2] * az;
        Cm[r * 3 + 0] = dp * ax - A[r * 3 + 0];
        Cm[r * 3 + 1] = dp * ay - A[r * 3 + 1];
        Cm[r * 3 + 2] = dp * az - A[r * 3 + 2];
    }

    float* base = csym + tid * 40;   // 10 float4 = 40 floats per joint

    if (tid < 6) {
        #pragma unroll
        for (int k = 0; k < 9; k++) {
            base[0  + k] = A[k];
            base[12 + k] = Bm[k];
            base[24 + k] = Cm[k];
        }
        base[9] = base[10] = base[11] = 0.f;
        base[21] = base[22] = base[23] = 0.f;
        base[33] = base[34] = base[35] = 0.f;
        base[36] = F[3]; base[37] = F[7]; base[38] = F[11]; base[39] = 0.f;
    } else {
        // joint 6 with F7 folded:
        // rot' = (A + sB + oC)*F7r  -> fold F7r into A,B,C
        // trans' = (A f7t + t6) + s (B f7t) + o (C f7t) = at + s*bt + o*ct
        const float* F7 = ft + 7 * 16;
        float F7r[9], f7t[3];
        #pragma unroll
        for (int r = 0; r < 3; r++) {
            #pragma unroll
            for (int c = 0; c < 3; c++)
                F7r[r * 3 + c] = F7[r * 4 + c];
            f7t[r] = F7[r * 4 + 3];
        }
        #pragma unroll
        for (int r = 0; r < 3; r++)
            #pragma unroll
            for (int c = 0; c < 3; c++) {
                base[0  + r * 3 + c] = A[r * 3 + 0] * F7r[c] + A[r * 3 + 1] * F7r[3 + c] + A[r * 3 + 2] * F7r[6 + c];
                base[12 + r * 3 + c] = Bm[r * 3 + 0] * F7r[c] + Bm[r * 3 + 1] * F7r[3 + c] + Bm[r * 3 + 2] * F7r[6 + c];
                base[24 + r * 3 + c] = Cm[r * 3 + 0] * F7r[c] + Cm[r * 3 + 1] * F7r[3 + c] + Cm[r * 3 + 2] * F7r[6 + c];
            }
        base[9] = base[10] = base[11] = 0.f;
        base[21] = base[22] = base[23] = 0.f;
        base[33] = base[34] = base[35] = 0.f;
        #pragma unroll
        for (int r = 0; r < 3; r++) {
            base[36 + r]       = A[r * 3 + 0] * f7t[0] + A[r * 3 + 1] * f7t[1] + A[r * 3 + 2] * f7t[2] + F[r * 4 + 3];  // at
            csym[280 + r]      = Bm[r * 3 + 0] * f7t[0] + Bm[r * 3 + 1] * f7t[1] + Bm[r * 3 + 2] * f7t[2];              // bt
            csym[284 + r]      = Cm[r * 3 + 0] * f7t[0] + Cm[r * 3 + 1] * f7t[1] + Cm[r * 3 + 2] * f7t[2];              // ct
        }
        base[39] = 0.f;
        csym[283] = 0.f; csym[287] = 0.f;
    }
}

__global__ __launch_bounds__(THREADS)
void fk_kernel(const float* __restrict__ jp,    // (B,7)
               float* __restrict__ out,         // (B,4,4)
               int n)
{
    const int n_idx = blockIdx.x * THREADS + threadIdx.x;
    if (n_idx >= n) return;

    const float* p = jp + (size_t)n_idx * NACT;
    float th[NACT];
    #pragma unroll
    for (int i = 0; i < NACT; i++) th[i] = p[i];

    float Tr[9], Tt[3];

    // joint 0: T = M0
    {
        float s, c;
        __sincosf(th[0], &s, &c);
        const float o = 1.0f - c;
        float4 a0 = cst4[0], a1 = cst4[1], a2 = cst4[2];
        float4 b0 = cst4[3], b1 = cst4[4], b2 = cst4[5];
        float4 c0 = cst4[6], c1 = cst4[7], c2 = cst4[8];
        Tr[0] = fmaf(o, c0.x, fmaf(s, b0.x, a0.x));
        Tr[1] = fmaf(o, c0.y, fmaf(s, b0.y, a0.y));
        Tr[2] = fmaf(o, c0.z, fmaf(s, b0.z, a0.z));
        Tr[3] = fmaf(o, c0.w, fmaf(s, b0.w, a0.w));
        Tr[4] = fmaf(o, c1.x, fmaf(s, b1.x, a1.x));
        Tr[5] = fmaf(o, c1.y, fmaf(s, b1.y, a1.y));
        Tr[6] = fmaf(o, c1.z, fmaf(s, b1.z, a1.z));
        Tr[7] = fmaf(o, c1.w, fmaf(s, b1.w, a1.w));
        Tr[8] = fmaf(o, c2.x, fmaf(s, b2.x, a2.x));
        float4 t = cst4[9];
        Tt[0] = t.x; Tt[1] = t.y; Tt[2] = t.z;
    }

    // joints 1..5: T = T @ Mi
    #pragma unroll
    for (int i = 1; i < 6; i++) {
        float s, c;
        __sincosf(th[i], &s, &c);
        const float o = 1.0f - c;
        float4 a0 = cst4[i * 10 + 0], a1 = cst4[i * 10 + 1], a2 = cst4[i * 10 + 2];
        float4 b0 = cst4[i * 10 + 3], b1 = cst4[i * 10 + 4], b2 = cst4[i * 10 + 5];
        float4 c0 = cst4[i * 10 + 6], c1 = cst4[i * 10 + 7], c2 = cst4[i * 10 + 8];
        float M[9];
        M[0] = fmaf(o, c0.x, fmaf(s, b0.x, a0.x));
        M[1] = fmaf(o, c0.y, fmaf(s, b0.y, a0.y));
        M[2] = fmaf(o, c0.z, fmaf(s, b0.z, a0.z));
        M[3] = fmaf(o, c0.w, fmaf(s, b0.w, a0.w));
        M[4] = fmaf(o, c1.x, fmaf(s, b1.x, a1.x));
        M[5] = fmaf(o, c1.y, fmaf(s, b1.y, a1.y));
        M[6] = fmaf(o, c1.z, fmaf(s, b1.z, a1.z));
        M[7] = fmaf(o, c1.w, fmaf(s, b1.w, a1.w));
        M[8] = fmaf(o, c2.x, fmaf(s, b2.x, a2.x));

        float R[9];
        #pragma unroll
        for (int r = 0; r < 3; r++)
            #pragma unroll
            for (int c2i = 0; c2i < 3; c2i++)
                R[r * 3 + c2i] = fmaf(Tr[r * 3 + 2], M[6 + c2i],
                                 fmaf(Tr[r * 3 + 1], M[3 + c2i],
                                      Tr[r * 3 + 0] * M[0 + c2i]));

        float4 t = cst4[i * 10 + 9];
        #pragma unroll
        for (int r = 0; r < 3; r++)
            Tt[r] = fmaf(Tr[r * 3 + 2], t.z,
                    fmaf(Tr[r * 3 + 1], t.y,
                    fmaf(Tr[r * 3 + 0], t.x, Tt[r])));

        #pragma unroll
        for (int k = 0; k < 9; k++) Tr[k] = R[k];
    }

    // joint 6 (F7 folded): rot from cst, trans = at + s*bt + o*ct
    float Rr[9], Ot[3];
    {
        float s, c;
        __sincosf(th[6], &s, &c);
        const float o = 1.0f - c;
        float4 a0 = cst4[60], a1 = cst4[61], a2 = cst4[62];
        float4 b0 = cst4[63], b1 = cst4[64], b2 = cst4[65];
        float4 c0 = cst4[66], c1 = cst4[67], c2 = cst4[68];
        float M[9];
        M[0] = fmaf(o, c0.x, fmaf(s, b0.x, a0.x));
        M[1] = fmaf(o, c0.y, fmaf(s, b0.y, a0.y));
        M[2] = fmaf(o, c0.z, fmaf(s, b0.z, a0.z));
        M[3] = fmaf(o, c0.w, fmaf(s, b0.w, a0.w));
        M[4] = fmaf(o, c1.x, fmaf(s, b1.x, a1.x));
        M[5] = fmaf(o, c1.y, fmaf(s, b1.y, a1.y));
        M[6] = fmaf(o, c1.z, fmaf(s, b1.z, a1.z));
        M[7] = fmaf(o, c1.w, fmaf(s, b1.w, a1.w));
        M[8] = fmaf(o, c2.x, fmaf(s, b2.x, a2.x));
        float4 at = cst4[69], bt = cst4[70], ct = cst4[71];
        float Mt[3];
        Mt[0] = fmaf(o, ct.x, fmaf(s, bt.x, at.x));
        Mt[1] = fmaf(o, ct.y, fmaf(s, bt.y, at.y));
        Mt[2] = fmaf(o, ct.z, fmaf(s, bt.z, at.z));

        #pragma unroll
        for (int r = 0; r < 3; r++) {
            #pragma unroll
            for (int c2i = 0; c2i < 3; c2i++)
                Rr[r * 3 + c2i] = fmaf(Tr[r * 3 + 2], M[6 + c2i],
                                  fmaf(Tr[r * 3 + 1], M[3 + c2i],
                                       Tr[r * 3 + 0] * M[0 + c2i]));
            Ot[r] = fmaf(Tr[r * 3 + 2], Mt[2],
                    fmaf(Tr[r * 3 + 1], Mt[1],
                    fmaf(Tr[r * 3 + 0], Mt[0], Tt[r])));
        }
    }

    float4* o = reinterpret_cast<float4*>(out + (size_t)n_idx * 16);
    o[0] = make_float4(Rr[0], Rr[1], Rr[2], Ot[0]);
    o[1] = make_float4(Rr[3], Rr[4], Rr[5], Ot[1]);
    o[2] = make_float4(Rr[6], Rr[7], Rr[8], Ot[2]);
    o[3] = make_float4(0.0f, 0.0f, 0.0f, 1.0f);
}

extern "C" void kernel_launch(void* const* d_in, const int* in_sizes, int n_in,
                              void* d_out, int out_size) {
    const float* jp   = (const float*)d_in[0];  // joint_positions (B,7)
    const float* ft   = (const float*)d_in[1];  // fixed_transforms (8,4,4)
    const float* axes = (const float*)d_in[2];  // joint_axes (7,3)
    float* out = (float*)d_out;
    const int n = in_sizes[0] / NACT;

    void* csym = nullptr;
    cudaGetSymbolAddress(&csym, cst4);   // backing store of __constant__ symbol

    prep_kernel<<<1, 32>>>(ft, axes, (float*)csym);

    const int blocks = (n + THREADS - 1) / THREADS;
    fk_kernel<<<blocks, THREADS>>>(jp, out, n);
}

// round 12
// speedup vs baseline: 1.0399x; 1.0399x over previous
#include <cuda_runtime.h>
#include <cuda_bf16.h>

// ForwardKinematics: B=524288, NA=7 joints, NJ=8 transforms.
// out[n] = M0*...*M6*F7, Mi = Fi*[[R(theta_i,a_i),0],[0,1]]
// rot(Mi) = A_i + sin*(A_i K_i) + (1-cos)*(A_i(aa^T) - A_i); trans(Mi)=t_i.
//
// R12 = R11 re-run (container infra failure, kernel untested): f32x2 packed
// math (halves FFMA stream; validated R5) + constant-port operands (zero
// L1tex; validated R9). Splatted float2(v,v) constants in __constant__ so
// each fma.rn.f32x2 reads its 64-bit constant off the constant port.
// 2 elements per thread (g, g+n/2). F7 folded into joint 6. No smem/barriers
// in hot kernel. Prep kernel writes directly into the __constant__ backing
// store (validated R10).

#define NACT 7
#define THREADS 256

// pair-index layout (each entry is float2(v,v)):
// joint i<6, base=i*30:  A[9] | B[9] | C[9] | t[3]
// joint 6,  base=180:    A[9] | B[9] | C[9] | at[3] | bt[3] | ct[3]
#define CST2_SIZE 216
__constant__ float2 cst2[CST2_SIZE];

typedef unsigned long long u64;

__device__ __forceinline__ u64 fma2(u64 a, u64 b, u64 c) {
    u64 d; asm("fma.rn.f32x2 %0, %1, %2, %3;" : "=l"(d) : "l"(a), "l"(b), "l"(c)); return d;
}
__device__ __forceinline__ u64 mul2(u64 a, u64 b) {
    u64 d; asm("mul.rn.f32x2 %0, %1, %2;" : "=l"(d) : "l"(a), "l"(b)); return d;
}
__device__ __forceinline__ u64 pack2(float lo, float hi) {
    u64 d; asm("mov.b64 %0, {%1, %2};" : "=l"(d) : "f"(lo), "f"(hi)); return d;
}
__device__ __forceinline__ float2 unpack2(u64 v) {
    float lo, hi; asm("mov.b64 {%0, %1}, %2;" : "=f"(lo), "=f"(hi) : "l"(v));
    return make_float2(lo, hi);
}
__device__ __forceinline__ u64 cread(int idx) {   // compile-time idx -> const-space 64-bit read
    return *reinterpret_cast<const u64*>(&cst2[idx]);
}

__global__ void prep_kernel(const float* __restrict__ ft,
                            const float* __restrict__ axes,
                            float2* __restrict__ c2)   // backing store of cst2
{
    const int tid = threadIdx.x;
    if (tid >= NACT) return;

    const float* F = ft + tid * 16;
    float A[9], Bm[9], Cm[9];
    #pragma unroll
    for (int r = 0; r < 3; r++)
        #pragma unroll
        for (int c = 0; c < 3; c++)
            A[r * 3 + c] = F[r * 4 + c];
    const float ax = axes[tid * 3 + 0];
    const float ay = axes[tid * 3 + 1];
    const float az = axes[tid * 3 + 2];
    #pragma unroll
    for (int r = 0; r < 3; r++) {
        Bm[r * 3 + 0] = A[r * 3 + 1] * az - A[r * 3 + 2] * ay;
        Bm[r * 3 + 1] = A[r * 3 + 2] * ax - A[r * 3 + 0] * az;
        Bm[r * 3 + 2] = A[r * 3 + 0] * ay - A[r * 3 + 1] * ax;
    }
    #pragma unroll
    for (int r = 0; r < 3; r++) {
        float dp = A[r * 3 + 0] * ax + A[r * 3 + 1] * ay + A[r * 3 + 2] * az;
        Cm[r * 3 + 0] = dp * ax - A[r * 3 + 0];
        Cm[r * 3 + 1] = dp * ay - A[r * 3 + 1];
        Cm[r * 3 + 2] = dp * az - A[r * 3 + 2];
    }

    if (tid < 6) {
        const int b = tid * 30;
        #pragma unroll
        for (int k = 0; k < 9; k++) {
            c2[b + k]      = make_float2(A[k], A[k]);
            c2[b + 9 + k]  = make_float2(Bm[k], Bm[k]);
            c2[b + 18 + k] = make_float2(Cm[k], Cm[k]);
        }
        c2[b + 27] = make_float2(F[3],  F[3]);
        c2[b + 28] = make_float2(F[7],  F[7]);
        c2[b + 29] = make_float2(F[11], F[11]);
    } else {
        // joint 6 with F7 folded:
        // rot' = (A + sB + oC)*F7r ; trans' = at + s*bt + o*ct
        const float* F7 = ft + 7 * 16;
        float F7r[9], f7t[3];
        #pragma unroll
        for (int r = 0; r < 3; r++) {
            #pragma unroll
            for (int c = 0; c < 3; c++)
                F7r[r * 3 + c] = F7[r * 4 + c];
            f7t[r] = F7[r * 4 + 3];
        }
        const int b = 180;
        #pragma unroll
        for (int r = 0; r < 3; r++)
            #pragma unroll
            for (int c = 0; c < 3; c++) {
                float ap = A[r * 3 + 0] * F7r[c] + A[r * 3 + 1] * F7r[3 + c] + A[r * 3 + 2] * F7r[6 + c];
                float bp = Bm[r * 3 + 0] * F7r[c] + Bm[r * 3 + 1] * F7r[3 + c] + Bm[r * 3 + 2] * F7r[6 + c];
                float cp = Cm[r * 3 + 0] * F7r[c] + Cm[r * 3 + 1] * F7r[3 + c] + Cm[r * 3 + 2] * F7r[6 + c];
                c2[b + r * 3 + c]      = make_float2(ap, ap);
                c2[b + 9 + r * 3 + c]  = make_float2(bp, bp);
                c2[b + 18 + r * 3 + c] = make_float2(cp, cp);
            }
        #pragma unroll
        for (int r = 0; r < 3; r++) {
            float at = A[r * 3 + 0] * f7t[0] + A[r * 3 + 1] * f7t[1] + A[r * 3 + 2] * f7t[2] + F[r * 4 + 3];
            float bt = Bm[r * 3 + 0] * f7t[0] + Bm[r * 3 + 1] * f7t[1] + Bm[r * 3 + 2] * f7t[2];
            float ct = Cm[r * 3 + 0] * f7t[0] + Cm[r * 3 + 1] * f7t[1] + Cm[r * 3 + 2] * f7t[2];
            c2[b + 27 + r] = make_float2(at, at);
            c2[b + 30 + r] = make_float2(bt, bt);
            c2[b + 33 + r] = make_float2(ct, ct);
        }
    }
}

__global__ __launch_bounds__(THREADS)
void fk_kernel(const float* __restrict__ jp,    // (B,7)
               float* __restrict__ out,         // (B,4,4)
               int n)
{
    const int half = n >> 1;   // B even
    const int g = blockIdx.x * THREADS + threadIdx.x;
    if (g >= half) return;

    const float* p0 = jp + (size_t)g * NACT;
    const float* p1 = jp + (size_t)(g + half) * NACT;
    float th0[NACT], th1[NACT];
    #pragma unroll
    for (int i = 0; i < NACT; i++) th0[i] = p0[i];
    #pragma unroll
    for (int i = 0; i < NACT; i++) th1[i] = p1[i];

    u64 Tr[9], Tt[3];

    // joint 0: T = M0
    {
        float s0, c0, s1, c1;
        __sincosf(th0[0], &s0, &c0);
        __sincosf(th1[0], &s1, &c1);
        u64 s2 = pack2(s0, s1);
        u64 o2 = pack2(1.0f - c0, 1.0f - c1);
        #pragma unroll
        for (int k = 0; k < 9; k++)
            Tr[k] = fma2(o2, cread(18 + k), fma2(s2, cread(9 + k), cread(k)));
        Tt[0] = cread(27); Tt[1] = cread(28); Tt[2] = cread(29);
    }

    // joints 1..5: T = T @ Mi
    #pragma unroll
    for (int i = 1; i < 6; i++) {
        float s0, c0, s1, c1;
        __sincosf(th0[i], &s0, &c0);
        __sincosf(th1[i], &s1, &c1);
        u64 s2 = pack2(s0, s1);
        u64 o2 = pack2(1.0f - c0, 1.0f - c1);
        const int b = i * 30;

        u64 M[9];
        #pragma unroll
        for (int k = 0; k < 9; k++)
            M[k] = fma2(o2, cread(b + 18 + k), fma2(s2, cread(b + 9 + k), cread(b + k)));

        u64 R[9];
        #pragma unroll
        for (int r = 0; r < 3; r++)
            #pragma unroll
            for (int c2i = 0; c2i < 3; c2i++)
                R[r * 3 + c2i] = fma2(Tr[r * 3 + 2], M[6 + c2i],
                                 fma2(Tr[r * 3 + 1], M[3 + c2i],
                                 mul2(Tr[r * 3 + 0], M[0 + c2i])));

        #pragma unroll
        for (int r = 0; r < 3; r++)
            Tt[r] = fma2(Tr[r * 3 + 2], cread(b + 29),
                    fma2(Tr[r * 3 + 1], cread(b + 28),
                    fma2(Tr[r * 3 + 0], cread(b + 27), Tt[r])));

        #pragma unroll
        for (int k = 0; k < 9; k++) Tr[k] = R[k];
    }

    // joint 6 (F7 folded): T = T @ M6'
    u64 Rr[9], Ot[3];
    {
        float s0, c0, s1, c1;
        __sincosf(th0[6], &s0, &c0);
        __sincosf(th1[6], &s1, &c1);
        u64 s2 = pack2(s0, s1);
        u64 o2 = pack2(1.0f - c0, 1.0f - c1);
        const int b = 180;

        u64 M[9], Mt[3];
        #pragma unroll
        for (int k = 0; k < 9; k++)
            M[k] = fma2(o2, cread(b + 18 + k), fma2(s2, cread(b + 9 + k), cread(b + k)));
        #pragma unroll
        for (int r = 0; r < 3; r++)
            Mt[r] = fma2(o2, cread(b + 33 + r), fma2(s2, cread(b + 30 + r), cread(b + 27 + r)));

        #pragma unroll
        for (int r = 0; r < 3; r++) {
            #pragma unroll
            for (int c2i = 0; c2i < 3; c2i++)
                Rr[r * 3 + c2i] = fma2(Tr[r * 3 + 2], M[6 + c2i],
                                  fma2(Tr[r * 3 + 1], M[3 + c2i],
                                  mul2(Tr[r * 3 + 0], M[0 + c2i])));
            Ot[r] = fma2(Tr[r * 3 + 2], Mt[2],
                    fma2(Tr[r * 3 + 1], Mt[1],
                    fma2(Tr[r * 3 + 0], Mt[0], Tt[r])));
        }
    }

    float2 rr[9], ot[3];
    #pragma unroll
    for (int k = 0; k < 9; k++) rr[k] = unpack2(Rr[k]);
    #pragma unroll
    for (int k = 0; k < 3; k++) ot[k] = unpack2(Ot[k]);

    {
        float4* o0 = reinterpret_cast<float4*>(out + (size_t)g * 16);
        o0[0] = make_float4(rr[0].x, rr[1].x, rr[2].x, ot[0].x);
        o0[1] = make_float4(rr[3].x, rr[4].x, rr[5].x, ot[1].x);
        o0[2] = make_float4(rr[6].x, rr[7].x, rr[8].x, ot[2].x);
        o0[3] = make_float4(0.0f, 0.0f, 0.0f, 1.0f);

        float4* o1 = reinterpret_cast<float4*>(out + (size_t)(g + half) * 16);
        o1[0] = make_float4(rr[0].y, rr[1].y, rr[2].y, ot[0].y);
        o1[1] = make_float4(rr[3].y, rr[4].y, rr[5].y, ot[1].y);
        o1[2] = make_float4(rr[6].y, rr[7].y, rr[8].y, ot[2].y);
        o1[3] = make_float4(0.0f, 0.0f, 0.0f, 1.0f);
    }
}

extern "C" void kernel_launch(void* const* d_in, const int* in_sizes, int n_in,
                              void* d_out, int out_size) {
    const float* jp   = (const float*)d_in[0];  // joint_positions (B,7)
    const float* ft   = (const float*)d_in[1];  // fixed_transforms (8,4,4)
    const float* axes = (const float*)d_in[2];  // joint_axes (7,3)
    float* out = (float*)d_out;
    const int n = in_sizes[0] / NACT;

    void* csym = nullptr;
    cudaGetSymbolAddress(&csym, cst2);   // backing store of __constant__ symbol

    prep_kernel<<<1, 32>>>(ft, axes, (float2*)csym);

    const int half = n >> 1;             // B is even
    const int blocks = (half + THREADS - 1) / THREADS;
    fk_kernel<<<blocks, THREADS>>>(jp, out, n);
}

// round 13
// speedup vs baseline: 1.1385x; 1.0949x over previous
#include <cuda_runtime.h>
#include <cuda_bf16.h>

// ForwardKinematics: B=524288, NA=7 joints, NJ=8 transforms.
// out[n] = M0*...*M6*F7, Mi = Fi*[[R(theta_i,a_i),0],[0,1]]
// rot(Mi) = A_i + sin*(A_i K_i) + (1-cos)*(A_i(aa^T) - A_i); trans(Mi)=t_i.
//
// R13: kernel is fma-PIPE-throughput bound (~360 FFMA/elem at rt=2/SMSP
// = 10.4us floor; running at ~70%). Single change vs R10: THREADS 256->128
// for finer regfile granularity (40 regs -> 12 CTAs/SM = 75% theoretical
// occupancy vs 61% measured) to close the pipe-efficiency gap.
// Constants in __constant__ (cbank), prep kernel writes backing store.

#define NACT 7
#define THREADS 128

// float4 layout: per joint i (i=0..6), base = i*10:
//   [0..2] A rows | [3..5] B=A@K | [6..8] C=A@(aa^T)-A | [9] t (j<6) / at (j6)
// [70] bt (joint 6), [71] ct (joint 6)
#define CST4_SIZE 72
__constant__ float4 cst4[CST4_SIZE];

__global__ void prep_kernel(const float* __restrict__ ft,
                            const float* __restrict__ axes,
                            float* __restrict__ csym)   // = &cst4 backing store
{
    const int tid = threadIdx.x;
    if (tid >= NACT) return;

    const float* F = ft + tid * 16;
    float A[9], Bm[9], Cm[9];
    #pragma unroll
    for (int r = 0; r < 3; r++)
        #pragma unroll
        for (int c = 0; c < 3; c++)
            A[r * 3 + c] = F[r * 4 + c];
    const float ax = axes[tid * 3 + 0];
    const float ay = axes[tid * 3 + 1];
    const float az = axes[tid * 3 + 2];
    #pragma unroll
    for (int r = 0; r < 3; r++) {
        Bm[r * 3 + 0] = A[r * 3 + 1] * az - A[r * 3 + 2] * ay;
        Bm[r * 3 + 1] = A[r * 3 + 2] * ax - A[r * 3 + 0] * az;
        Bm[r * 3 + 2] = A[r * 3 + 0] * ay - A[r * 3 + 1] * ax;
    }
    #pragma unroll
    for (int r = 0; r < 3; r++) {
        float dp = A[r * 3 + 0] * ax + A[r * 3 + 1] * ay + A[r * 3 + 2] * az;
        Cm[r * 3 + 0] = dp * ax - A[r * 3 + 0];
        Cm[r * 3 + 1] = dp * ay - A[r * 3 + 1];
        Cm[r * 3 + 2] = dp * az - A[r * 3 + 2];
    }

    float* base = csym + tid * 40;   // 10 float4 = 40 floats per joint

    if (tid < 6) {
        #pragma unroll
        for (int k = 0; k < 9; k++) {
            base[0  + k] = A[k];
            base[12 + k] = Bm[k];
            base[24 + k] = Cm[k];
        }
        base[9] = base[10] = base[11] = 0.f;
        base[21] = base[22] = base[23] = 0.f;
        base[33] = base[34] = base[35] = 0.f;
        base[36] = F[3]; base[37] = F[7]; base[38] = F[11]; base[39] = 0.f;
    } else {
        // joint 6 with F7 folded:
        // rot' = (A + sB + oC)*F7r ; trans' = at + s*bt + o*ct
        const float* F7 = ft + 7 * 16;
        float F7r[9], f7t[3];
        #pragma unroll
        for (int r = 0; r < 3; r++) {
            #pragma unroll
            for (int c = 0; c < 3; c++)
                F7r[r * 3 + c] = F7[r * 4 + c];
            f7t[r] = F7[r * 4 + 3];
        }
        #pragma unroll
        for (int r = 0; r < 3; r++)
            #pragma unroll
            for (int c = 0; c < 3; c++) {
                base[0  + r * 3 + c] = A[r * 3 + 0] * F7r[c] + A[r * 3 + 1] * F7r[3 + c] + A[r * 3 + 2] * F7r[6 + c];
                base[12 + r * 3 + c] = Bm[r * 3 + 0] * F7r[c] + Bm[r * 3 + 1] * F7r[3 + c] + Bm[r * 3 + 2] * F7r[6 + c];
                base[24 + r * 3 + c] = Cm[r * 3 + 0] * F7r[c] + Cm[r * 3 + 1] * F7r[3 + c] + Cm[r * 3 + 2] * F7r[6 + c];
            }
        base[9] = base[10] = base[11] = 0.f;
        base[21] = base[22] = base[23] = 0.f;
        base[33] = base[34] = base[35] = 0.f;
        #pragma unroll
        for (int r = 0; r < 3; r++) {
            base[36 + r] = A[r * 3 + 0] * f7t[0] + A[r * 3 + 1] * f7t[1] + A[r * 3 + 2] * f7t[2] + F[r * 4 + 3];  // at
            csym[280 + r] = Bm[r * 3 + 0] * f7t[0] + Bm[r * 3 + 1] * f7t[1] + Bm[r * 3 + 2] * f7t[2];             // bt
            csym[284 + r] = Cm[r * 3 + 0] * f7t[0] + Cm[r * 3 + 1] * f7t[1] + Cm[r * 3 + 2] * f7t[2];             // ct
        }
        base[39] = 0.f;
        csym[283] = 0.f; csym[287] = 0.f;
    }
}

__global__ __launch_bounds__(THREADS)
void fk_kernel(const float* __restrict__ jp,    // (B,7)
               float* __restrict__ out,         // (B,4,4)
               int n)
{
    const int n_idx = blockIdx.x * THREADS + threadIdx.x;
    if (n_idx >= n) return;

    const float* p = jp + (size_t)n_idx * NACT;
    float th[NACT];
    #pragma unroll
    for (int i = 0; i < NACT; i++) th[i] = p[i];

    float Tr[9], Tt[3];

    // joint 0: T = M0
    {
        float s, c;
        __sincosf(th[0], &s, &c);
        const float o = 1.0f - c;
        float4 a0 = cst4[0], a1 = cst4[1], a2 = cst4[2];
        float4 b0 = cst4[3], b1 = cst4[4], b2 = cst4[5];
        float4 c0 = cst4[6], c1 = cst4[7], c2 = cst4[8];
        Tr[0] = fmaf(o, c0.x, fmaf(s, b0.x, a0.x));
        Tr[1] = fmaf(o, c0.y, fmaf(s, b0.y, a0.y));
        Tr[2] = fmaf(o, c0.z, fmaf(s, b0.z, a0.z));
        Tr[3] = fmaf(o, c0.w, fmaf(s, b0.w, a0.w));
        Tr[4] = fmaf(o, c1.x, fmaf(s, b1.x, a1.x));
        Tr[5] = fmaf(o, c1.y, fmaf(s, b1.y, a1.y));
        Tr[6] = fmaf(o, c1.z, fmaf(s, b1.z, a1.z));
        Tr[7] = fmaf(o, c1.w, fmaf(s, b1.w, a1.w));
        Tr[8] = fmaf(o, c2.x, fmaf(s, b2.x, a2.x));
        float4 t = cst4[9];
        Tt[0] = t.x; Tt[1] = t.y; Tt[2] = t.z;
    }

    // joints 1..5: T = T @ Mi
    #pragma unroll
    for (int i = 1; i < 6; i++) {
        float s, c;
        __sincosf(th[i], &s, &c);
        const float o = 1.0f - c;
        float4 a0 = cst4[i * 10 + 0], a1 = cst4[i * 10 + 1], a2 = cst4[i * 10 + 2];
        float4 b0 = cst4[i * 10 + 3], b1 = cst4[i * 10 + 4], b2 = cst4[i * 10 + 5];
        float4 c0 = cst4[i * 10 + 6], c1 = cst4[i * 10 + 7], c2 = cst4[i * 10 + 8];
        float M[9];
        M[0] = fmaf(o, c0.x, fmaf(s, b0.x, a0.x));
        M[1] = fmaf(o, c0.y, fmaf(s, b0.y, a0.y));
        M[2] = fmaf(o, c0.z, fmaf(s, b0.z, a0.z));
        M[3] = fmaf(o, c0.w, fmaf(s, b0.w, a0.w));
        M[4] = fmaf(o, c1.x, fmaf(s, b1.x, a1.x));
        M[5] = fmaf(o, c1.y, fmaf(s, b1.y, a1.y));
        M[6] = fmaf(o, c1.z, fmaf(s, b1.z, a1.z));
        M[7] = fmaf(o, c1.w, fmaf(s, b1.w, a1.w));
        M[8] = fmaf(o, c2.x, fmaf(s, b2.x, a2.x));

        float R[9];
        #pragma unroll
        for (int r = 0; r < 3; r++)
            #pragma unroll
            for (int c2i = 0; c2i < 3; c2i++)
                R[r * 3 + c2i] = fmaf(Tr[r * 3 + 2], M[6 + c2i],
                                 fmaf(Tr[r * 3 + 1], M[3 + c2i],
                                      Tr[r * 3 + 0] * M[0 + c2i]));

        float4 t = cst4[i * 10 + 9];
        #pragma unroll
        for (int r = 0; r < 3; r++)
            Tt[r] = fmaf(Tr[r * 3 + 2], t.z,
                    fmaf(Tr[r * 3 + 1], t.y,
                    fmaf(Tr[r * 3 + 0], t.x, Tt[r])));

        #pragma unroll
        for (int k = 0; k < 9; k++) Tr[k] = R[k];
    }

    // joint 6 (F7 folded): rot from cst, trans = at + s*bt + o*ct
    float Rr[9], Ot[3];
    {
        float s, c;
        __sincosf(th[6], &s, &c);
        const float o = 1.0f - c;
        float4 a0 = cst4[60], a1 = cst4[61], a2 = cst4[62];
        float4 b0 = cst4[63], b1 = cst4[64], b2 = cst4[65];
        float4 c0 = cst4[66], c1 = cst4[67], c2 = cst4[68];
        float M[9];
        M[0] = fmaf(o, c0.x, fmaf(s, b0.x, a0.x));
        M[1] = fmaf(o, c0.y, fmaf(s, b0.y, a0.y));
        M[2] = fmaf(o, c0.z, fmaf(s, b0.z, a0.z));
        M[3] = fmaf(o, c0.w, fmaf(s, b0.w, a0.w));
        M[4] = fmaf(o, c1.x, fmaf(s, b1.x, a1.x));
        M[5] = fmaf(o, c1.y, fmaf(s, b1.y, a1.y));
        M[6] = fmaf(o, c1.z, fmaf(s, b1.z, a1.z));
        M[7] = fmaf(o, c1.w, fmaf(s, b1.w, a1.w));
        M[8] = fmaf(o, c2.x, fmaf(s, b2.x, a2.x));
        float4 at = cst4[69], bt = cst4[70], ct = cst4[71];
        float Mt[3];
        Mt[0] = fmaf(o, ct.x, fmaf(s, bt.x, at.x));
        Mt[1] = fmaf(o, ct.y, fmaf(s, bt.y, at.y));
        Mt[2] = fmaf(o, ct.z, fmaf(s, bt.z, at.z));

        #pragma unroll
        for (int r = 0; r < 3; r++) {
            #pragma unroll
            for (int c2i = 0; c2i < 3; c2i++)
                Rr[r * 3 + c2i] = fmaf(Tr[r * 3 + 2], M[6 + c2i],
                                  fmaf(Tr[r * 3 + 1], M[3 + c2i],
                                       Tr[r * 3 + 0] * M[0 + c2i]));
            Ot[r] = fmaf(Tr[r * 3 + 2], Mt[2],
                    fmaf(Tr[r * 3 + 1], Mt[1],
                    fmaf(Tr[r * 3 + 0], Mt[0], Tt[r])));
        }
    }

    float4* o = reinterpret_cast<float4*>(out + (size_t)n_idx * 16);
    o[0] = make_float4(Rr[0], Rr[1], Rr[2], Ot[0]);
    o[1] = make_float4(Rr[3], Rr[4], Rr[5], Ot[1]);
    o[2] = make_float4(Rr[6], Rr[7], Rr[8], Ot[2]);
    o[3] = make_float4(0.0f, 0.0f, 0.0f, 1.0f);
}

extern "C" void kernel_launch(void* const* d_in, const int* in_sizes, int n_in,
                              void* d_out, int out_size) {
    const float* jp   = (const float*)d_in[0];  // joint_positions (B,7)
    const float* ft   = (const float*)d_in[1];  // fixed_transforms (8,4,4)
    const float* axes = (const float*)d_in[2];  // joint_axes (7,3)
    float* out = (float*)d_out;
    const int n = in_sizes[0] / NACT;

    void* csym = nullptr;
    cudaGetSymbolAddress(&csym, cst4);   // backing store of __constant__ symbol

    prep_kernel<<<1, 32>>>(ft, axes, (float*)csym);

    const int blocks = (n + THREADS - 1) / THREADS;
    fk_kernel<<<blocks, THREADS>>>(jp, out, n);
}